// round 2
// baseline (speedup 1.0000x reference)
#include <cuda_runtime.h>
#include <cuda_bf16.h>
#include <stdint.h>

// Problem shapes (fixed by the reference)
#define D_K      128
#define HALF_D   64            // d_k/2 rotation pairs
#define SEQ_LEN  4096
#define BATCH    4
#define N_HEADS  16
#define TOTAL_ELEMS (BATCH * N_HEADS * SEQ_LEN * D_K)   // 33,554,432 floats
#define TOTAL_VEC4  (TOTAL_ELEMS / 4)                    // 8,388,608 float4
#define VEC4_PER_THREAD 2

// Scratch: per-position (cos, sin) pairs, interleaved so one float4 load
// yields {cos0, sin0, cos1, sin1} for two adjacent rotation pairs.
// Size: 4096 * 64 * 2 floats = 2 MB (L2-resident during kernel 2).
__device__ float g_cs_table[SEQ_LEN * HALF_D * 2];

// ---------------------------------------------------------------------------
// Kernel 1: extract cos/sin from the block-diagonal rotation matrices.
//   cos(s, k) = R[pos[s], 2k,   2k]
//   sin(s, k) = R[pos[s], 2k+1, 2k]
// One thread per (s, k). 262,144 threads; scattered LDG but tiny traffic
// (~16 MB of 32B sectors). Using the reference's own cos/sin values keeps
// bit-exact agreement with the matvec formulation.
// ---------------------------------------------------------------------------
__global__ void build_cs_table_kernel(const float* __restrict__ ro_weights,
                                      const int* __restrict__ token_positions)
{
    int idx = blockIdx.x * blockDim.x + threadIdx.x;   // 0 .. SEQ_LEN*HALF_D-1
    if (idx >= SEQ_LEN * HALF_D) return;
    int s = idx >> 6;          // / HALF_D
    int k = idx & (HALF_D - 1);

    int pos = token_positions[s];
    const float* Rrow = ro_weights + (size_t)pos * D_K * D_K;
    int ev = 2 * k;
    float c  = __ldg(Rrow + ev * D_K + ev);           // R[pos, 2k,   2k] = cos
    float sn = __ldg(Rrow + (ev + 1) * D_K + ev);     // R[pos, 2k+1, 2k] = sin

    g_cs_table[idx * 2 + 0] = c;
    g_cs_table[idx * 2 + 1] = sn;
}

// ---------------------------------------------------------------------------
// Kernel 2: apply RoPE. Pure streaming, float4-vectorized, 2 vec4/thread
// for MLP_p1=4 (2 x-loads + 2 table-loads batched up front).
//   out_e = c*x_e - s*x_o ;  out_o = s*x_e + c*x_o
// Index math: 32 float4 per 128-wide row; s = (i >> 5) & 4095.
// ---------------------------------------------------------------------------
__global__ void __launch_bounds__(256) rope_apply_kernel(
    const float4* __restrict__ x4,
    float4* __restrict__ out4)
{
    int base = (blockIdx.x * blockDim.x + threadIdx.x) * VEC4_PER_THREAD;
    if (base >= TOTAL_VEC4) return;

    const float4* tbl4 = reinterpret_cast<const float4*>(g_cs_table);

    int i0 = base;
    int i1 = base + 1;

    // Batch all loads up front (independent → MLP=4)
    float4 v0 = x4[i0];
    float4 v1 = x4[i1];
    int s0 = (i0 >> 5) & (SEQ_LEN - 1);
    int s1 = (i1 >> 5) & (SEQ_LEN - 1);
    float4 cs0 = __ldg(tbl4 + s0 * 32 + (i0 & 31));   // {c0, s0, c1, s1}
    float4 cs1 = __ldg(tbl4 + s1 * 32 + (i1 & 31));

    float4 r0, r1;
    r0.x = cs0.x * v0.x - cs0.y * v0.y;
    r0.y = cs0.y * v0.x + cs0.x * v0.y;
    r0.z = cs0.z * v0.z - cs0.w * v0.w;
    r0.w = cs0.w * v0.z + cs0.z * v0.w;

    r1.x = cs1.x * v1.x - cs1.y * v1.y;
    r1.y = cs1.y * v1.x + cs1.x * v1.y;
    r1.z = cs1.z * v1.z - cs1.w * v1.w;
    r1.w = cs1.w * v1.z + cs1.z * v1.w;

    out4[i0] = r0;
    out4[i1] = r1;
}

// ---------------------------------------------------------------------------
// Launch. Inputs (metadata order): x [B,H,S,D] f32, token_positions [S] i32,
// ro_weights [4096,128,128] f32. Output: [B,H,S,D] f32.
// ---------------------------------------------------------------------------
extern "C" void kernel_launch(void* const* d_in, const int* in_sizes, int n_in,
                              void* d_out, int out_size)
{
    const float* x          = (const float*)d_in[0];
    const int*   tok_pos    = (const int*)d_in[1];
    const float* ro_weights = (const float*)d_in[2];

    // Kernel 1: build (cos,sin) table — 262144 threads
    {
        int n = SEQ_LEN * HALF_D;
        int threads = 256;
        int blocks = (n + threads - 1) / threads;
        build_cs_table_kernel<<<blocks, threads>>>(ro_weights, tok_pos);
    }

    // Kernel 2: apply rotation — 8,388,608 float4, 2 per thread
    {
        int threads = 256;
        int total_threads = TOTAL_VEC4 / VEC4_PER_THREAD;   // 4,194,304
        int blocks = total_threads / threads;               // 16,384 (exact)
        rope_apply_kernel<<<blocks, threads>>>(
            reinterpret_cast<const float4*>(x),
            reinterpret_cast<float4*>((float*)d_out));
    }
}

// round 6
// speedup vs baseline: 1.0762x; 1.0762x over previous
#include <cuda_runtime.h>
#include <cuda_bf16.h>
#include <stdint.h>

// Problem shapes (fixed by the reference)
#define D_K      128
#define HALF_D   64
#define SEQ_LEN  4096
#define BATCH    4
#define N_HEADS  16
#define N_ROWS   (BATCH * N_HEADS)        // 64 rows (b,h) per position s
#define VEC4_PER_ROW 32                   // 128 floats / 4
#define ROW_STRIDE_V4 (SEQ_LEN * VEC4_PER_ROW)  // 131072 vec4 between (b,h) rows

#define THREADS 512
#define ROWS_PER_ITER (THREADS / 32)      // 16 rows covered per pass

// ---------------------------------------------------------------------------
// Fused kernel: one block per position s.
//
// Phase 1: threads 0..127 gather this position's 128 cos/sin values from the
//   block-diagonal rotation matrix into smem. Address identity:
//     t even (t=2k):   R[pos, t,   t] = cos_k
//     t odd  (t=2k+1): R[pos, t, t-1] = sin_k
//   both collapse to offset  pos*16384 + t*129 - (t&1),
//   so smem lands in interleaved {c,s,c,s,...} layout: a float4 read at
//   vec4-column c gives {cos0,sin0,cos1,sin1} for two rotation pairs.
//   Gather latency overlaps with streaming work of other resident blocks.
//
// Phase 2: stream all 64 (b,h) rows for this s. Each warp covers one row's
//   512 contiguous bytes (fully coalesced); each thread keeps a fixed
//   column so the cs value is read from smem once. The 4 x-loads (rows
//   w, w+16, w+32, w+48 — 32 MB apart, independent) are batched for MLP=4.
// ---------------------------------------------------------------------------
__global__ void __launch_bounds__(THREADS) rope_fused_kernel(
    const float4* __restrict__ x4,
    float4* __restrict__ out4,
    const float* __restrict__ ro_weights,
    const int* __restrict__ token_positions)
{
    __shared__ float cs_s[D_K];

    const int s   = blockIdx.x;
    const int tid = threadIdx.x;

    // ---- Phase 1: gather cos/sin for this position ----
    if (tid < D_K) {
        int pos = token_positions[s];                      // broadcast load
        size_t off = (size_t)pos * (D_K * D_K) + tid * (D_K + 1) - (tid & 1);
        cs_s[tid] = __ldg(ro_weights + off);
    }
    __syncthreads();

    // ---- Phase 2: stream the 64 rows ----
    const int col = tid & 31;          // fixed vec4 column for this thread
    const int w   = tid >> 5;          // warp id = row offset within pass

    const float4* cs4 = reinterpret_cast<const float4*>(cs_s);
    const float4 cs = cs4[col];        // {c0, s0, c1, s1}

    // base vec4 index for row r: r*ROW_STRIDE_V4 + s*32 + col
    const int base = w * ROW_STRIDE_V4 + s * VEC4_PER_ROW + col;

    // Batch all 4 independent x-loads (MLP=4)
    float4 v0 = x4[base + 0 * ROWS_PER_ITER * ROW_STRIDE_V4];
    float4 v1 = x4[base + 1 * ROWS_PER_ITER * ROW_STRIDE_V4];
    float4 v2 = x4[base + 2 * ROWS_PER_ITER * ROW_STRIDE_V4];
    float4 v3 = x4[base + 3 * ROWS_PER_ITER * ROW_STRIDE_V4];

    float4 r0, r1, r2, r3;
    r0.x = cs.x * v0.x - cs.y * v0.y;  r0.y = cs.y * v0.x + cs.x * v0.y;
    r0.z = cs.z * v0.z - cs.w * v0.w;  r0.w = cs.w * v0.z + cs.z * v0.w;

    r1.x = cs.x * v1.x - cs.y * v1.y;  r1.y = cs.y * v1.x + cs.x * v1.y;
    r1.z = cs.z * v1.z - cs.w * v1.w;  r1.w = cs.w * v1.z + cs.z * v1.w;

    r2.x = cs.x * v2.x - cs.y * v2.y;  r2.y = cs.y * v2.x + cs.x * v2.y;
    r2.z = cs.z * v2.z - cs.w * v2.w;  r2.w = cs.w * v2.z + cs.z * v2.w;

    r3.x = cs.x * v3.x - cs.y * v3.y;  r3.y = cs.y * v3.x + cs.x * v3.y;
    r3.z = cs.z * v3.z - cs.w * v3.w;  r3.w = cs.w * v3.z + cs.z * v3.w;

    out4[base + 0 * ROWS_PER_ITER * ROW_STRIDE_V4] = r0;
    out4[base + 1 * ROWS_PER_ITER * ROW_STRIDE_V4] = r1;
    out4[base + 2 * ROWS_PER_ITER * ROW_STRIDE_V4] = r2;
    out4[base + 3 * ROWS_PER_ITER * ROW_STRIDE_V4] = r3;
}

// ---------------------------------------------------------------------------
// Launch. Inputs (metadata order): x [B,H,S,D] f32, token_positions [S] i32,
// ro_weights [4096,128,128] f32. Output: [B,H,S,D] f32.
// ---------------------------------------------------------------------------
extern "C" void kernel_launch(void* const* d_in, const int* in_sizes, int n_in,
                              void* d_out, int out_size)
{
    const float* x          = (const float*)d_in[0];
    const int*   tok_pos    = (const int*)d_in[1];
    const float* ro_weights = (const float*)d_in[2];

    rope_fused_kernel<<<SEQ_LEN, THREADS>>>(
        reinterpret_cast<const float4*>(x),
        reinterpret_cast<float4*>((float*)d_out),
        ro_weights,
        tok_pos);
}